// round 12
// baseline (speedup 1.0000x reference)
#include <cuda_runtime.h>
#include <cuda_fp16.h>
#include <cstdint>

#define D 64
#define N_MAX 200000
#define E_MAX 4000000
#define SCAN_T 1024

// ---- scratch (static device globals; zero-initialized at module load) ----
__device__ int     g_deg[N_MAX];       // zeroed at load; re-zeroed by k_final each call
__device__ int     g_off[N_MAX];
__device__ float   g_dinv[N_MAX];
__device__ __align__(16) int g_rank[E_MAX];     // per-edge rank within its dst bucket
__device__ __align__(16) int g_src[E_MAX];      // CSR adjacency: src only
__device__ __half2 g_s0[(size_t)N_MAX * 32];    // s0 = dinv ⊙ emb0 (fp16)
__device__ __half2 g_s1h[(size_t)N_MAX * 32];   // s1 fp16 (for final combine)
__device__ __half2 g_s2h[(size_t)N_MAX * 32];   // s2 fp16 (for final combine)
__device__ __align__(16) uchar4 g_q1[(size_t)N_MAX * 16];  // s1 int8 rows (for gathers)
__device__ __align__(16) uchar4 g_q2[(size_t)N_MAX * 16];  // s2 int8 rows
__device__ float   g_sc1[N_MAX];                // per-row scales
__device__ float   g_sc2[N_MAX];
__device__ int     g_bsum[256];

// ---------------- degree count + rank record, 8 edges/thread ----------------
__global__ void k_count(const int* __restrict__ dst, int E) {
    int i = (blockIdx.x * blockDim.x + threadIdx.x) * 8;
    if (i + 7 < E) {
        int4 d0 = *reinterpret_cast<const int4*>(dst + i);
        int4 d1 = *reinterpret_cast<const int4*>(dst + i + 4);
        int4 r0, r1;
        r0.x = atomicAdd(&g_deg[d0.x], 1);
        r0.y = atomicAdd(&g_deg[d0.y], 1);
        r0.z = atomicAdd(&g_deg[d0.z], 1);
        r0.w = atomicAdd(&g_deg[d0.w], 1);
        r1.x = atomicAdd(&g_deg[d1.x], 1);
        r1.y = atomicAdd(&g_deg[d1.y], 1);
        r1.z = atomicAdd(&g_deg[d1.z], 1);
        r1.w = atomicAdd(&g_deg[d1.w], 1);
        *reinterpret_cast<int4*>(g_rank + i)     = r0;
        *reinterpret_cast<int4*>(g_rank + i + 4) = r1;
    } else {
        for (; i < E; ++i) g_rank[i] = atomicAdd(&g_deg[dst[i]], 1);
    }
}

// ---------------- block-local exclusive scan + dinv fused ----------------
__global__ void k_scanA(int n) {
    __shared__ int s[SCAN_T];
    int t = threadIdx.x;
    int i = blockIdx.x * SCAN_T + t;
    int v = (i < n) ? g_deg[i] : 0;
    s[t] = v;
    __syncthreads();
    for (int d = 1; d < SCAN_T; d <<= 1) {
        int x = (t >= d) ? s[t - d] : 0;
        __syncthreads();
        s[t] += x;
        __syncthreads();
    }
    if (i < n) {
        g_off[i]  = s[t] - v;
        g_dinv[i] = (v > 0) ? rsqrtf((float)v) : 0.0f;
    }
    if (t == SCAN_T - 1) g_bsum[blockIdx.x] = s[t];
}

// ------- merged scanB+scanC + fused init (out0 = emb0, g_s0 = dinv ⊙ emb0) -------
__global__ void k_scanBC(int n, int nb, const float4* __restrict__ emb,
                         float4* __restrict__ o0, int n4) {
    __shared__ int s[256];
    int t = threadIdx.x;
    if (t < 256) s[t] = (t < nb) ? g_bsum[t] : 0;
    __syncthreads();
    for (int d = 1; d < 256; d <<= 1) {
        int x = (t < 256 && t >= d) ? s[t - d] : 0;
        __syncthreads();
        if (t < 256) s[t] += x;
        __syncthreads();
    }
    int excl = s[blockIdx.x] - g_bsum[blockIdx.x];
    int i = blockIdx.x * SCAN_T + t;
    if (i < n) g_off[i] += excl;

    int stride = gridDim.x * blockDim.x;
    for (int k = blockIdx.x * blockDim.x + t; k < n4; k += stride) {
        float4 v = emb[k];
        o0[k] = v;
        float dv = g_dinv[k >> 4];
        g_s0[2 * k]     = __float22half2_rn(make_float2(v.x * dv, v.y * dv));
        g_s0[2 * k + 1] = __float22half2_rn(make_float2(v.z * dv, v.w * dv));
    }
}

// ---------------- CSR fill: NO atomic — pos = off[dst] + rank, 8 edges/thread ----------------
__global__ void k_fill(const int* __restrict__ src,
                       const int* __restrict__ dst, int E) {
    int i = (blockIdx.x * blockDim.x + threadIdx.x) * 8;
    if (i + 7 < E) {
        int4 d0 = *reinterpret_cast<const int4*>(dst + i);
        int4 d1 = *reinterpret_cast<const int4*>(dst + i + 4);
        int4 s0 = *reinterpret_cast<const int4*>(src + i);
        int4 s1 = *reinterpret_cast<const int4*>(src + i + 4);
        int4 r0 = *reinterpret_cast<const int4*>(g_rank + i);
        int4 r1 = *reinterpret_cast<const int4*>(g_rank + i + 4);
        g_src[g_off[d0.x] + r0.x] = s0.x;
        g_src[g_off[d0.y] + r0.y] = s0.y;
        g_src[g_off[d0.z] + r0.z] = s0.z;
        g_src[g_off[d0.w] + r0.w] = s0.w;
        g_src[g_off[d1.x] + r1.x] = s1.x;
        g_src[g_off[d1.y] + r1.y] = s1.y;
        g_src[g_off[d1.z] + r1.z] = s1.z;
        g_src[g_off[d1.w] + r1.w] = s1.w;
    } else {
        for (; i < E; ++i) g_src[g_off[dst[i]] + g_rank[i]] = src[i];
    }
}

// ---------------- fp16 gather-sum (layer 1): half-warp per edge ----------------
#define ACC(r) do { \
    float2 _fa = __half22float2(*reinterpret_cast<__half2*>(&(r).x)); \
    float2 _fb = __half22float2(*reinterpret_cast<__half2*>(&(r).y)); \
    ax += _fa.x; ay += _fa.y; az += _fb.x; aw += _fb.y; } while (0)

__device__ __forceinline__ float4 gather_sum2(const uint2* __restrict__ in2,
                                              int lo, int end, int side, int sub) {
    float ax = 0.f, ay = 0.f, az = 0.f, aw = 0.f;
    int j = lo;
    while (j < end && (j & 3)) {
        if ((j & 1) == side) {
            uint2 r = in2[(((size_t)g_src[j]) << 4) + sub];
            ACC(r);
        }
        ++j;
    }
    const int4* __restrict__ s4 = reinterpret_cast<const int4*>(g_src);
    for (; j + 16 <= end; j += 16) {
        int4 a = s4[(j >> 2) + 0];
        int4 b = s4[(j >> 2) + 1];
        int4 c = s4[(j >> 2) + 2];
        int4 d = s4[(j >> 2) + 3];
        int i0 = side ? a.y : a.x;
        int i1 = side ? a.w : a.z;
        int i2 = side ? b.y : b.x;
        int i3 = side ? b.w : b.z;
        int i4 = side ? c.y : c.x;
        int i5 = side ? c.w : c.z;
        int i6 = side ? d.y : d.x;
        int i7 = side ? d.w : d.z;
        uint2 r0 = in2[(((size_t)i0) << 4) + sub];
        uint2 r1 = in2[(((size_t)i1) << 4) + sub];
        uint2 r2 = in2[(((size_t)i2) << 4) + sub];
        uint2 r3 = in2[(((size_t)i3) << 4) + sub];
        uint2 r4 = in2[(((size_t)i4) << 4) + sub];
        uint2 r5 = in2[(((size_t)i5) << 4) + sub];
        uint2 r6 = in2[(((size_t)i6) << 4) + sub];
        uint2 r7 = in2[(((size_t)i7) << 4) + sub];
        ACC(r0); ACC(r1); ACC(r2); ACC(r3);
        ACC(r4); ACC(r5); ACC(r6); ACC(r7);
    }
    for (; j + 4 <= end; j += 4) {
        int4 a = s4[j >> 2];
        int i0 = side ? a.y : a.x;
        int i1 = side ? a.w : a.z;
        uint2 r0 = in2[(((size_t)i0) << 4) + sub];
        uint2 r1 = in2[(((size_t)i1) << 4) + sub];
        ACC(r0); ACC(r1);
    }
    while (j < end) {
        if ((j & 1) == side) {
            uint2 r = in2[(((size_t)g_src[j]) << 4) + sub];
            ACC(r);
        }
        ++j;
    }
    ax += __shfl_xor_sync(0xffffffffu, ax, 16);
    ay += __shfl_xor_sync(0xffffffffu, ay, 16);
    az += __shfl_xor_sync(0xffffffffu, az, 16);
    aw += __shfl_xor_sync(0xffffffffu, aw, 16);
    return make_float4(ax, ay, az, aw);
}

// ---------------- int8 gather-sum (layers 2/3): 64B rows + per-row scale ----------------
#define ACCQ(r, c) do { \
    char4 _c = *reinterpret_cast<char4*>(&(r)); \
    ax = fmaf((float)_c.x, (c), ax); \
    ay = fmaf((float)_c.y, (c), ay); \
    az = fmaf((float)_c.z, (c), az); \
    aw = fmaf((float)_c.w, (c), aw); } while (0)

__device__ __forceinline__ float4 gather_sum_q(const uchar4* __restrict__ q,
                                               const float* __restrict__ sc,
                                               int lo, int end, int side, int sub) {
    float ax = 0.f, ay = 0.f, az = 0.f, aw = 0.f;
    int j = lo;
    while (j < end && (j & 3)) {
        if ((j & 1) == side) {
            int s = g_src[j];
            uchar4 r = q[(((size_t)s) << 4) + sub];
            float c = sc[s];
            ACCQ(r, c);
        }
        ++j;
    }
    const int4* __restrict__ s4 = reinterpret_cast<const int4*>(g_src);
    for (; j + 16 <= end; j += 16) {
        int4 a = s4[(j >> 2) + 0];
        int4 b = s4[(j >> 2) + 1];
        int4 c = s4[(j >> 2) + 2];
        int4 d = s4[(j >> 2) + 3];
        int i0 = side ? a.y : a.x;
        int i1 = side ? a.w : a.z;
        int i2 = side ? b.y : b.x;
        int i3 = side ? b.w : b.z;
        int i4 = side ? c.y : c.x;
        int i5 = side ? c.w : c.z;
        int i6 = side ? d.y : d.x;
        int i7 = side ? d.w : d.z;
        uchar4 r0 = q[(((size_t)i0) << 4) + sub];  float c0 = sc[i0];
        uchar4 r1 = q[(((size_t)i1) << 4) + sub];  float c1 = sc[i1];
        uchar4 r2 = q[(((size_t)i2) << 4) + sub];  float c2 = sc[i2];
        uchar4 r3 = q[(((size_t)i3) << 4) + sub];  float c3 = sc[i3];
        uchar4 r4 = q[(((size_t)i4) << 4) + sub];  float c4 = sc[i4];
        uchar4 r5 = q[(((size_t)i5) << 4) + sub];  float c5 = sc[i5];
        uchar4 r6 = q[(((size_t)i6) << 4) + sub];  float c6 = sc[i6];
        uchar4 r7 = q[(((size_t)i7) << 4) + sub];  float c7 = sc[i7];
        ACCQ(r0, c0); ACCQ(r1, c1); ACCQ(r2, c2); ACCQ(r3, c3);
        ACCQ(r4, c4); ACCQ(r5, c5); ACCQ(r6, c6); ACCQ(r7, c7);
    }
    for (; j + 4 <= end; j += 4) {
        int4 a = s4[j >> 2];
        int i0 = side ? a.y : a.x;
        int i1 = side ? a.w : a.z;
        uchar4 r0 = q[(((size_t)i0) << 4) + sub];  float c0 = sc[i0];
        uchar4 r1 = q[(((size_t)i1) << 4) + sub];  float c1 = sc[i1];
        ACCQ(r0, c0); ACCQ(r1, c1);
    }
    while (j < end) {
        if ((j & 1) == side) {
            int s = g_src[j];
            uchar4 r = q[(((size_t)s) << 4) + sub];
            float c = sc[s];
            ACCQ(r, c);
        }
        ++j;
    }
    ax += __shfl_xor_sync(0xffffffffu, ax, 16);
    ay += __shfl_xor_sync(0xffffffffu, ay, 16);
    az += __shfl_xor_sync(0xffffffffu, az, 16);
    aw += __shfl_xor_sync(0xffffffffu, aw, 16);
    return make_float4(ax, ay, az, aw);
}

// -------- dual write: fp16 row + int8 row with per-row scale (all lanes hold full sums) --------
__device__ __forceinline__ void dual_store(float4 s, int warp, int lane, int side, int sub,
                                           __half2* __restrict__ sh,
                                           uchar4* __restrict__ q,
                                           float* __restrict__ sc) {
    // row max over 16 subs (both halves hold identical values after xor16)
    float m = fmaxf(fmaxf(fabsf(s.x), fabsf(s.y)), fmaxf(fabsf(s.z), fabsf(s.w)));
    m = fmaxf(m, __shfl_xor_sync(0xffffffffu, m, 1));
    m = fmaxf(m, __shfl_xor_sync(0xffffffffu, m, 2));
    m = fmaxf(m, __shfl_xor_sync(0xffffffffu, m, 4));
    m = fmaxf(m, __shfl_xor_sync(0xffffffffu, m, 8));
    float inv = (m > 0.f) ? 127.0f / m : 0.f;
    if (side == 0) {
        __half2 oa = __float22half2_rn(make_float2(s.x, s.y));
        __half2 ob = __float22half2_rn(make_float2(s.z, s.w));
        uint2 o;
        o.x = *reinterpret_cast<unsigned*>(&oa);
        o.y = *reinterpret_cast<unsigned*>(&ob);
        reinterpret_cast<uint2*>(sh)[(((size_t)warp) << 4) + sub] = o;
        char4 cq;
        cq.x = (char)__float2int_rn(s.x * inv);
        cq.y = (char)__float2int_rn(s.y * inv);
        cq.z = (char)__float2int_rn(s.z * inv);
        cq.w = (char)__float2int_rn(s.w * inv);
        *reinterpret_cast<char4*>(&q[(((size_t)warp) << 4) + sub]) = cq;
        if (lane == 0) sc[warp] = (m > 0.f) ? m * (1.0f / 127.0f) : 0.f;
    }
}

// layer 1: gather fp16 s0 -> s1 (fp16 + int8)
__global__ void __launch_bounds__(256) k_prop_a(const __half2* __restrict__ in,
                                                __half2* __restrict__ s1h,
                                                uchar4* __restrict__ q1,
                                                float* __restrict__ sc1, int n) {
    int warp = (blockIdx.x * blockDim.x + threadIdx.x) >> 5;
    int lane = threadIdx.x & 31;
    if (warp >= n) return;
    int side = lane >> 4, sub = lane & 15;
    int lo = g_off[warp];
    float4 s = gather_sum2(reinterpret_cast<const uint2*>(in),
                           lo, lo + g_deg[warp], side, sub);
    float dv = g_dinv[warp];
    float d2 = dv * dv;
    s.x *= d2; s.y *= d2; s.z *= d2; s.w *= d2;
    dual_store(s, warp, lane, side, sub, s1h, q1, sc1);
}

// layer 2: gather int8 q1 -> s2 (fp16 + int8)
__global__ void __launch_bounds__(256) k_prop_b(const uchar4* __restrict__ q1,
                                                const float* __restrict__ sc1,
                                                __half2* __restrict__ s2h,
                                                uchar4* __restrict__ q2,
                                                float* __restrict__ sc2, int n) {
    int warp = (blockIdx.x * blockDim.x + threadIdx.x) >> 5;
    int lane = threadIdx.x & 31;
    if (warp >= n) return;
    int side = lane >> 4, sub = lane & 15;
    int lo = g_off[warp];
    float4 s = gather_sum_q(q1, sc1, lo, lo + g_deg[warp], side, sub);
    float dv = g_dinv[warp];
    float d2 = dv * dv;
    s.x *= d2; s.y *= d2; s.z *= d2; s.w *= d2;
    dual_store(s, warp, lane, side, sub, s2h, q2, sc2);
}

// final: out = (emb0 + (s1+s2)*sqrt(deg) + dinv*Σ q2[src]) * 0.25; re-zero g_deg
__global__ void __launch_bounds__(256) k_final(const float* __restrict__ emb0,
                                               const __half2* __restrict__ s1h,
                                               const __half2* __restrict__ s2h,
                                               const uchar4* __restrict__ q2,
                                               const float* __restrict__ sc2,
                                               float* __restrict__ outp, int n) {
    int warp = (blockIdx.x * blockDim.x + threadIdx.x) >> 5;
    int lane = threadIdx.x & 31;
    if (warp >= n) return;
    int side = lane >> 4, sub = lane & 15;
    int lo = g_off[warp];
    int dg = g_deg[warp];
    float4 s = gather_sum_q(q2, sc2, lo, lo + dg, side, sub);

    if (side == 0) {
        float dv = g_dinv[warp];
        float sq = sqrtf((float)dg);               // e_k = s_k * sqrt(deg)
        size_t ro = (((size_t)warp) << 4) + sub;
        float4 e0 = reinterpret_cast<const float4*>(emb0)[ro];
        uint2 r1 = reinterpret_cast<const uint2*>(s1h)[ro];
        uint2 r2 = reinterpret_cast<const uint2*>(s2h)[ro];
        float2 a1a = __half22float2(*reinterpret_cast<__half2*>(&r1.x));
        float2 a1b = __half22float2(*reinterpret_cast<__half2*>(&r1.y));
        float2 a2a = __half22float2(*reinterpret_cast<__half2*>(&r2.x));
        float2 a2b = __half22float2(*reinterpret_cast<__half2*>(&r2.y));
        float4 r;
        r.x = (e0.x + (a1a.x + a2a.x) * sq + s.x * dv) * 0.25f;
        r.y = (e0.y + (a1a.y + a2a.y) * sq + s.y * dv) * 0.25f;
        r.z = (e0.z + (a1b.x + a2b.x) * sq + s.z * dv) * 0.25f;
        r.w = (e0.w + (a1b.y + a2b.y) * sq + s.w * dv) * 0.25f;
        reinterpret_cast<float4*>(outp)[ro] = r;
    }
    if (lane == 0) g_deg[warp] = 0;   // restore invariant for next graph replay
}

extern "C" void kernel_launch(void* const* d_in, const int* in_sizes, int n_in,
                              void* d_out, int out_size) {
    const int*   edges = (const int*)d_in[0];       // int32
    const float* emb   = (const float*)d_in[1];
    int E = in_sizes[0] / 2;
    int N = in_sizes[1] / D;

    const int* src = edges;
    const int* dst = edges + E;

    float* out0 = (float*)d_out;
    float* outp = out0 + (size_t)N * D;

    int tb = 256;
    int nbE8 = ((E + 7) / 8 + tb - 1) / tb;         // 8 edges per thread
    int NB   = (N + SCAN_T - 1) / SCAN_T;
    int n4   = (N * D) / 4;

    k_count<<<nbE8, tb>>>(dst, E);                                  // launch 0
    k_scanA<<<NB, SCAN_T>>>(N);                                     // launch 1
    k_scanBC<<<NB, SCAN_T>>>(N, NB, (const float4*)emb,
                             (float4*)out0, n4);                    // launch 2 (+init)
    k_fill<<<nbE8, tb>>>(src, dst, E);                              // launch 3

    __half2 *s0p, *s1p, *s2p;
    uchar4  *q1p, *q2p;
    float   *c1p, *c2p;
    cudaGetSymbolAddress((void**)&s0p, g_s0);
    cudaGetSymbolAddress((void**)&s1p, g_s1h);
    cudaGetSymbolAddress((void**)&s2p, g_s2h);
    cudaGetSymbolAddress((void**)&q1p, g_q1);
    cudaGetSymbolAddress((void**)&q2p, g_q2);
    cudaGetSymbolAddress((void**)&c1p, g_sc1);
    cudaGetSymbolAddress((void**)&c2p, g_sc2);

    int pthreads = N * 32;                          // one warp per node
    int pblocks  = (pthreads + tb - 1) / tb;
    k_prop_a<<<pblocks, tb>>>(s0p, s1p, q1p, c1p, N);               // launch 4
    k_prop_b<<<pblocks, tb>>>(q1p, c1p, s2p, q2p, c2p, N);          // launch 5
    k_final<<<pblocks, tb>>>(emb, s1p, s2p, q2p, c2p, outp, N);     // launch 6
}

// round 13
// speedup vs baseline: 1.0284x; 1.0284x over previous
#include <cuda_runtime.h>
#include <cuda_fp16.h>
#include <cstdint>

#define D 64
#define N_MAX 200000
#define E_MAX 4000000
#define SCAN_T 1024

// ---- scratch (static device globals; zero-initialized at module load) ----
__device__ int     g_deg[N_MAX];       // zeroed at load; re-zeroed by k_final each call
__device__ int     g_off[N_MAX];
__device__ float   g_dinv[N_MAX];
__device__ __align__(16) int g_rank[E_MAX];     // per-edge rank within its dst bucket
__device__ __align__(16) int g_src[E_MAX];      // CSR adjacency: src only
__device__ __half2 g_s0[(size_t)N_MAX * 32];    // s0 = dinv ⊙ emb0 (fp16)
__device__ __half2 g_s1[(size_t)N_MAX * 32];    // s1 = dinv ⊙ e1
__device__ __half2 g_s2[(size_t)N_MAX * 32];    // s2 = dinv ⊙ e2
__device__ int     g_bsum[256];

// ---------------- degree count + rank record, 4 edges/thread ----------------
__global__ void k_count(const int* __restrict__ dst, int E) {
    int i = (blockIdx.x * blockDim.x + threadIdx.x) * 4;
    if (i + 3 < E) {
        int4 d = *reinterpret_cast<const int4*>(dst + i);
        int4 r;
        r.x = atomicAdd(&g_deg[d.x], 1);
        r.y = atomicAdd(&g_deg[d.y], 1);
        r.z = atomicAdd(&g_deg[d.z], 1);
        r.w = atomicAdd(&g_deg[d.w], 1);
        *reinterpret_cast<int4*>(g_rank + i) = r;
    } else {
        for (; i < E; ++i) g_rank[i] = atomicAdd(&g_deg[dst[i]], 1);
    }
}

// ---------------- block-local exclusive scan + dinv fused ----------------
__global__ void k_scanA(int n) {
    __shared__ int s[SCAN_T];
    int t = threadIdx.x;
    int i = blockIdx.x * SCAN_T + t;
    int v = (i < n) ? g_deg[i] : 0;
    s[t] = v;
    __syncthreads();
    for (int d = 1; d < SCAN_T; d <<= 1) {
        int x = (t >= d) ? s[t - d] : 0;
        __syncthreads();
        s[t] += x;
        __syncthreads();
    }
    if (i < n) {
        g_off[i]  = s[t] - v;
        g_dinv[i] = (v > 0) ? rsqrtf((float)v) : 0.0f;
    }
    if (t == SCAN_T - 1) g_bsum[blockIdx.x] = s[t];
}

// ------- merged scanB+scanC + fused init (out0 = emb0, g_s0 = dinv ⊙ emb0) -------
__global__ void k_scanBC(int n, int nb, const float4* __restrict__ emb,
                         float4* __restrict__ o0, int n4) {
    __shared__ int s[256];
    int t = threadIdx.x;
    if (t < 256) s[t] = (t < nb) ? g_bsum[t] : 0;
    __syncthreads();
    for (int d = 1; d < 256; d <<= 1) {
        int x = (t < 256 && t >= d) ? s[t - d] : 0;
        __syncthreads();
        if (t < 256) s[t] += x;
        __syncthreads();
    }
    int excl = s[blockIdx.x] - g_bsum[blockIdx.x];
    int i = blockIdx.x * SCAN_T + t;
    if (i < n) g_off[i] += excl;

    int stride = gridDim.x * blockDim.x;
    for (int k = blockIdx.x * blockDim.x + t; k < n4; k += stride) {
        float4 v = emb[k];
        o0[k] = v;
        float dv = g_dinv[k >> 4];
        g_s0[2 * k]     = __float22half2_rn(make_float2(v.x * dv, v.y * dv));
        g_s0[2 * k + 1] = __float22half2_rn(make_float2(v.z * dv, v.w * dv));
    }
}

// ---------------- CSR fill: NO atomic — pos = off[dst] + rank, 4 edges/thread ----------------
__global__ void k_fill(const int* __restrict__ src,
                       const int* __restrict__ dst, int E) {
    int i = (blockIdx.x * blockDim.x + threadIdx.x) * 4;
    if (i + 3 < E) {
        int4 d = *reinterpret_cast<const int4*>(dst + i);
        int4 s = *reinterpret_cast<const int4*>(src + i);
        int4 r = *reinterpret_cast<const int4*>(g_rank + i);
        g_src[g_off[d.x] + r.x] = s.x;
        g_src[g_off[d.y] + r.y] = s.y;
        g_src[g_off[d.z] + r.z] = s.z;
        g_src[g_off[d.w] + r.w] = s.w;
    } else {
        for (; i < E; ++i) g_src[g_off[dst[i]] + g_rank[i]] = src[i];
    }
}

// ------------- gather-sum: warp per node, QUARTER-warp (8 lanes x 16B) per edge -------------
// Each lane loads one uint4 = 4 half2 = 8 consecutive halves of its edge's row.
// qw = lane>>3 selects which of 4 concurrent edges; reduce across qws via xor8/xor16.
#define ACC4(r) do { \
    float2 _f0 = __half22float2(*reinterpret_cast<__half2*>(&(r).x)); \
    float2 _f1 = __half22float2(*reinterpret_cast<__half2*>(&(r).y)); \
    float2 _f2 = __half22float2(*reinterpret_cast<__half2*>(&(r).z)); \
    float2 _f3 = __half22float2(*reinterpret_cast<__half2*>(&(r).w)); \
    a0 += _f0.x; a1 += _f0.y; a2 += _f1.x; a3 += _f1.y; \
    a4 += _f2.x; a5 += _f2.y; a6 += _f3.x; a7 += _f3.y; } while (0)

#define PICK(v4) (qw == 0 ? (v4).x : qw == 1 ? (v4).y : qw == 2 ? (v4).z : (v4).w)

__device__ __forceinline__ void gather_sum4(const uint4* __restrict__ in4,
                                            int lo, int end, int qw, int sub,
                                            float* acc) {
    float a0 = 0.f, a1 = 0.f, a2 = 0.f, a3 = 0.f;
    float a4 = 0.f, a5 = 0.f, a6 = 0.f, a7 = 0.f;
    int j = lo;
    // peel to 4-aligned edge index (qw 0 handles strays)
    while (j < end && (j & 3)) {
        if (qw == 0) {
            uint4 r = in4[(((size_t)g_src[j]) << 3) + sub];
            ACC4(r);
        }
        ++j;
    }
    const int4* __restrict__ s4 = reinterpret_cast<const int4*>(g_src);
    // 16 edges per trip: 4 int4 index loads, 4 gather LDG.128 in flight per lane
    for (; j + 16 <= end; j += 16) {
        int4 a = s4[(j >> 2) + 0];
        int4 b = s4[(j >> 2) + 1];
        int4 c = s4[(j >> 2) + 2];
        int4 d = s4[(j >> 2) + 3];
        int i0 = PICK(a);
        int i1 = PICK(b);
        int i2 = PICK(c);
        int i3 = PICK(d);
        uint4 r0 = in4[(((size_t)i0) << 3) + sub];
        uint4 r1 = in4[(((size_t)i1) << 3) + sub];
        uint4 r2 = in4[(((size_t)i2) << 3) + sub];
        uint4 r3 = in4[(((size_t)i3) << 3) + sub];
        ACC4(r0); ACC4(r1); ACC4(r2); ACC4(r3);
    }
    // 4-edge tail trips
    for (; j + 4 <= end; j += 4) {
        int4 a = s4[j >> 2];
        int i0 = PICK(a);
        uint4 r = in4[(((size_t)i0) << 3) + sub];
        ACC4(r);
    }
    // final singles
    while (j < end) {
        if (qw == 0) {
            uint4 r = in4[(((size_t)g_src[j]) << 3) + sub];
            ACC4(r);
        }
        ++j;
    }
    // reduce across the 4 quarter-warps (same sub)
    a0 += __shfl_xor_sync(0xffffffffu, a0, 8);
    a1 += __shfl_xor_sync(0xffffffffu, a1, 8);
    a2 += __shfl_xor_sync(0xffffffffu, a2, 8);
    a3 += __shfl_xor_sync(0xffffffffu, a3, 8);
    a4 += __shfl_xor_sync(0xffffffffu, a4, 8);
    a5 += __shfl_xor_sync(0xffffffffu, a5, 8);
    a6 += __shfl_xor_sync(0xffffffffu, a6, 8);
    a7 += __shfl_xor_sync(0xffffffffu, a7, 8);
    a0 += __shfl_xor_sync(0xffffffffu, a0, 16);
    a1 += __shfl_xor_sync(0xffffffffu, a1, 16);
    a2 += __shfl_xor_sync(0xffffffffu, a2, 16);
    a3 += __shfl_xor_sync(0xffffffffu, a3, 16);
    a4 += __shfl_xor_sync(0xffffffffu, a4, 16);
    a5 += __shfl_xor_sync(0xffffffffu, a5, 16);
    a6 += __shfl_xor_sync(0xffffffffu, a6, 16);
    a7 += __shfl_xor_sync(0xffffffffu, a7, 16);
    acc[0] = a0; acc[1] = a1; acc[2] = a2; acc[3] = a3;
    acc[4] = a4; acc[5] = a5; acc[6] = a6; acc[7] = a7;
}

// layers 0/1: s_out[v] = fp16( dinv[v]^2 * Σ s_in[src] )   [invariant: s = dinv ⊙ e]
__global__ void __launch_bounds__(256) k_prop(const __half2* __restrict__ in,
                                              __half2* __restrict__ out, int n) {
    int warp = (blockIdx.x * blockDim.x + threadIdx.x) >> 5;
    int lane = threadIdx.x & 31;
    if (warp >= n) return;
    int qw = lane >> 3, sub = lane & 7;
    int lo = g_off[warp];
    float acc[8];
    gather_sum4(reinterpret_cast<const uint4*>(in), lo, lo + g_deg[warp], qw, sub, acc);
    if (qw == 0) {
        float dv = g_dinv[warp];
        float d2 = dv * dv;
        __half2 h0 = __float22half2_rn(make_float2(acc[0] * d2, acc[1] * d2));
        __half2 h1 = __float22half2_rn(make_float2(acc[2] * d2, acc[3] * d2));
        __half2 h2 = __float22half2_rn(make_float2(acc[4] * d2, acc[5] * d2));
        __half2 h3 = __float22half2_rn(make_float2(acc[6] * d2, acc[7] * d2));
        uint4 o;
        o.x = *reinterpret_cast<unsigned*>(&h0);
        o.y = *reinterpret_cast<unsigned*>(&h1);
        o.z = *reinterpret_cast<unsigned*>(&h2);
        o.w = *reinterpret_cast<unsigned*>(&h3);
        reinterpret_cast<uint4*>(out)[(((size_t)warp) << 3) + sub] = o;
    }
}

// final: out = (emb0 + (s1+s2)*sqrt(deg) + dinv*Σ s2[src]) * 0.25; re-zero g_deg
__global__ void __launch_bounds__(256) k_final(const float* __restrict__ emb0,
                                               float* __restrict__ outp, int n) {
    int warp = (blockIdx.x * blockDim.x + threadIdx.x) >> 5;
    int lane = threadIdx.x & 31;
    if (warp >= n) return;
    int qw = lane >> 3, sub = lane & 7;
    int lo = g_off[warp];
    int dg = g_deg[warp];
    float acc[8];
    gather_sum4(reinterpret_cast<const uint4*>(g_s2), lo, lo + dg, qw, sub, acc);

    if (qw == 0) {
        float dv = g_dinv[warp];
        float sq = sqrtf((float)dg);               // e_k = s_k * sqrt(deg)
        size_t ro = (((size_t)warp) << 3) + sub;   // uint4 index into half rows
        uint4 r1 = reinterpret_cast<const uint4*>(g_s1)[ro];
        uint4 r2 = reinterpret_cast<const uint4*>(g_s2)[ro];
        // emb0/out rows: 64 floats; lane covers floats sub*8 .. sub*8+7
        const float4* e0p = reinterpret_cast<const float4*>(emb0) + (((size_t)warp) << 4) + (sub << 1);
        float4* op = reinterpret_cast<float4*>(outp) + (((size_t)warp) << 4) + (sub << 1);
        float4 e0a = e0p[0];
        float4 e0b = e0p[1];
        float2 f10 = __half22float2(*reinterpret_cast<__half2*>(&r1.x));
        float2 f11 = __half22float2(*reinterpret_cast<__half2*>(&r1.y));
        float2 f12 = __half22float2(*reinterpret_cast<__half2*>(&r1.z));
        float2 f13 = __half22float2(*reinterpret_cast<__half2*>(&r1.w));
        float2 f20 = __half22float2(*reinterpret_cast<__half2*>(&r2.x));
        float2 f21 = __half22float2(*reinterpret_cast<__half2*>(&r2.y));
        float2 f22 = __half22float2(*reinterpret_cast<__half2*>(&r2.z));
        float2 f23 = __half22float2(*reinterpret_cast<__half2*>(&r2.w));
        float4 ra, rb;
        ra.x = (e0a.x + (f10.x + f20.x) * sq + acc[0] * dv) * 0.25f;
        ra.y = (e0a.y + (f10.y + f20.y) * sq + acc[1] * dv) * 0.25f;
        ra.z = (e0a.z + (f11.x + f21.x) * sq + acc[2] * dv) * 0.25f;
        ra.w = (e0a.w + (f11.y + f21.y) * sq + acc[3] * dv) * 0.25f;
        rb.x = (e0b.x + (f12.x + f22.x) * sq + acc[4] * dv) * 0.25f;
        rb.y = (e0b.y + (f12.y + f22.y) * sq + acc[5] * dv) * 0.25f;
        rb.z = (e0b.z + (f13.x + f23.x) * sq + acc[6] * dv) * 0.25f;
        rb.w = (e0b.w + (f13.y + f23.y) * sq + acc[7] * dv) * 0.25f;
        op[0] = ra;
        op[1] = rb;
    }
    if (lane == 0) g_deg[warp] = 0;   // restore invariant for next graph replay
}

extern "C" void kernel_launch(void* const* d_in, const int* in_sizes, int n_in,
                              void* d_out, int out_size) {
    const int*   edges = (const int*)d_in[0];       // int32
    const float* emb   = (const float*)d_in[1];
    int E = in_sizes[0] / 2;
    int N = in_sizes[1] / D;

    const int* src = edges;
    const int* dst = edges + E;

    float* out0 = (float*)d_out;
    float* outp = out0 + (size_t)N * D;

    int tb = 256;
    int nbE4 = ((E + 3) / 4 + tb - 1) / tb;         // 4 edges per thread
    int NB   = (N + SCAN_T - 1) / SCAN_T;
    int n4   = (N * D) / 4;

    k_count<<<nbE4, tb>>>(dst, E);                                  // launch 0
    k_scanA<<<NB, SCAN_T>>>(N);                                     // launch 1
    k_scanBC<<<NB, SCAN_T>>>(N, NB, (const float4*)emb,
                             (float4*)out0, n4);                    // launch 2 (+init)
    k_fill<<<nbE4, tb>>>(src, dst, E);                              // launch 3

    __half2 *s0p, *s1p, *s2p;
    cudaGetSymbolAddress((void**)&s0p, g_s0);
    cudaGetSymbolAddress((void**)&s1p, g_s1);
    cudaGetSymbolAddress((void**)&s2p, g_s2);

    int pthreads = N * 32;                          // one warp per node
    int pblocks  = (pthreads + tb - 1) / tb;
    k_prop<<<pblocks, tb>>>(s0p, s1p, N);           // launch 4
    k_prop<<<pblocks, tb>>>(s1p, s2p, N);           // launch 5
    k_final<<<pblocks, tb>>>(emb, outp, N);         // launch 6
}

// round 14
// speedup vs baseline: 1.1157x; 1.0849x over previous
#include <cuda_runtime.h>
#include <cuda_fp16.h>
#include <cstdint>

#define D 64
#define N_MAX 200000
#define E_MAX 4000000
#define SCAN_T 1024

// ---- scratch (static device globals; zero-initialized at module load) ----
__device__ int     g_deg[N_MAX];       // zeroed at load; re-zeroed by k_final each call
__device__ int     g_off[N_MAX];
__device__ float   g_dinv[N_MAX];
__device__ __align__(16) int g_rank[E_MAX];     // per-edge rank within its dst bucket
__device__ __align__(16) int g_src[E_MAX];      // CSR adjacency: src only
__device__ __half2 g_s0[(size_t)N_MAX * 32];    // s0 = dinv ⊙ emb0 (fp16)
__device__ __half2 g_s1[(size_t)N_MAX * 32];    // s1 = dinv ⊙ e1
__device__ __half2 g_s2[(size_t)N_MAX * 32];    // s2 = dinv ⊙ e2
__device__ int     g_bsum[256];

// ------- degree count + rank record (4 edges/thread) + fused out0 copy -------
// The atomic chain is latency-bound (issue ~3%); the out0 streaming copy rides
// in its shadow using otherwise-idle issue slots.
__global__ void k_count(const int* __restrict__ dst, int E,
                        const float4* __restrict__ emb, float4* __restrict__ o0,
                        int n4) {
    int tid = blockIdx.x * blockDim.x + threadIdx.x;
    int i = tid * 4;
    if (i + 3 < E) {
        int4 d = *reinterpret_cast<const int4*>(dst + i);
        int4 r;
        r.x = atomicAdd(&g_deg[d.x], 1);
        r.y = atomicAdd(&g_deg[d.y], 1);
        r.z = atomicAdd(&g_deg[d.z], 1);
        r.w = atomicAdd(&g_deg[d.w], 1);
        *reinterpret_cast<int4*>(g_rank + i) = r;
    } else {
        for (int k = i; k < E; ++k) g_rank[k] = atomicAdd(&g_deg[dst[k]], 1);
    }
    // fused: out0 = emb0 (independent of everything)
    int stride = gridDim.x * blockDim.x;
    for (int k = tid; k < n4; k += stride) o0[k] = emb[k];
}

// ---------------- block-local exclusive scan + dinv fused ----------------
__global__ void k_scanA(int n) {
    __shared__ int s[SCAN_T];
    int t = threadIdx.x;
    int i = blockIdx.x * SCAN_T + t;
    int v = (i < n) ? g_deg[i] : 0;
    s[t] = v;
    __syncthreads();
    for (int d = 1; d < SCAN_T; d <<= 1) {
        int x = (t >= d) ? s[t - d] : 0;
        __syncthreads();
        s[t] += x;
        __syncthreads();
    }
    if (i < n) {
        g_off[i]  = s[t] - v;
        g_dinv[i] = (v > 0) ? rsqrtf((float)v) : 0.0f;
    }
    if (t == SCAN_T - 1) g_bsum[blockIdx.x] = s[t];
}

// ---------------- merged scanB+scanC (scan finalize only; light) ----------------
__global__ void k_scanBC(int n, int nb) {
    __shared__ int s[256];
    int t = threadIdx.x;
    if (t < 256) s[t] = (t < nb) ? g_bsum[t] : 0;
    __syncthreads();
    for (int d = 1; d < 256; d <<= 1) {
        int x = (t < 256 && t >= d) ? s[t - d] : 0;
        __syncthreads();
        if (t < 256) s[t] += x;
        __syncthreads();
    }
    int excl = s[blockIdx.x] - g_bsum[blockIdx.x];
    int i = blockIdx.x * SCAN_T + t;
    if (i < n) g_off[i] += excl;
}

// ------- CSR fill (no atomic; 4 edges/thread) + fused s0 build -------
// The scattered rank-writes are latency-bound; the s0 conversion (needs dinv,
// ready since scanA) streams in their shadow.
__global__ void k_fill(const int* __restrict__ src,
                       const int* __restrict__ dst, int E,
                       const float4* __restrict__ emb, int n4) {
    int tid = blockIdx.x * blockDim.x + threadIdx.x;
    int i = tid * 4;
    if (i + 3 < E) {
        int4 d = *reinterpret_cast<const int4*>(dst + i);
        int4 s = *reinterpret_cast<const int4*>(src + i);
        int4 r = *reinterpret_cast<const int4*>(g_rank + i);
        g_src[g_off[d.x] + r.x] = s.x;
        g_src[g_off[d.y] + r.y] = s.y;
        g_src[g_off[d.z] + r.z] = s.z;
        g_src[g_off[d.w] + r.w] = s.w;
    } else {
        for (int k = i; k < E; ++k) g_src[g_off[dst[k]] + g_rank[k]] = src[k];
    }
    // fused: g_s0 = fp16(dinv ⊙ emb0)
    int stride = gridDim.x * blockDim.x;
    for (int k = tid; k < n4; k += stride) {
        float4 v = emb[k];
        float dv = g_dinv[k >> 4];                 // 16 float4 per node row
        g_s0[2 * k]     = __float22half2_rn(make_float2(v.x * dv, v.y * dv));
        g_s0[2 * k + 1] = __float22half2_rn(make_float2(v.z * dv, v.w * dv));
    }
}

// ---------------- gather-sum: warp per node, half-warp per edge (R11 optimum) ----------------
#define ACC(r) do { \
    float2 _fa = __half22float2(*reinterpret_cast<__half2*>(&(r).x)); \
    float2 _fb = __half22float2(*reinterpret_cast<__half2*>(&(r).y)); \
    ax += _fa.x; ay += _fa.y; az += _fb.x; aw += _fb.y; } while (0)

__device__ __forceinline__ float4 gather_sum2(const uint2* __restrict__ in2,
                                              int lo, int end, int side, int sub) {
    float ax = 0.f, ay = 0.f, az = 0.f, aw = 0.f;
    int j = lo;
    while (j < end && (j & 3)) {
        if ((j & 1) == side) {
            uint2 r = in2[(((size_t)g_src[j]) << 4) + sub];
            ACC(r);
        }
        ++j;
    }
    const int4* __restrict__ s4 = reinterpret_cast<const int4*>(g_src);
    for (; j + 16 <= end; j += 16) {
        int4 a = s4[(j >> 2) + 0];
        int4 b = s4[(j >> 2) + 1];
        int4 c = s4[(j >> 2) + 2];
        int4 d = s4[(j >> 2) + 3];
        int i0 = side ? a.y : a.x;
        int i1 = side ? a.w : a.z;
        int i2 = side ? b.y : b.x;
        int i3 = side ? b.w : b.z;
        int i4 = side ? c.y : c.x;
        int i5 = side ? c.w : c.z;
        int i6 = side ? d.y : d.x;
        int i7 = side ? d.w : d.z;
        uint2 r0 = in2[(((size_t)i0) << 4) + sub];
        uint2 r1 = in2[(((size_t)i1) << 4) + sub];
        uint2 r2 = in2[(((size_t)i2) << 4) + sub];
        uint2 r3 = in2[(((size_t)i3) << 4) + sub];
        uint2 r4 = in2[(((size_t)i4) << 4) + sub];
        uint2 r5 = in2[(((size_t)i5) << 4) + sub];
        uint2 r6 = in2[(((size_t)i6) << 4) + sub];
        uint2 r7 = in2[(((size_t)i7) << 4) + sub];
        ACC(r0); ACC(r1); ACC(r2); ACC(r3);
        ACC(r4); ACC(r5); ACC(r6); ACC(r7);
    }
    for (; j + 4 <= end; j += 4) {
        int4 a = s4[j >> 2];
        int i0 = side ? a.y : a.x;
        int i1 = side ? a.w : a.z;
        uint2 r0 = in2[(((size_t)i0) << 4) + sub];
        uint2 r1 = in2[(((size_t)i1) << 4) + sub];
        ACC(r0); ACC(r1);
    }
    while (j < end) {
        if ((j & 1) == side) {
            uint2 r = in2[(((size_t)g_src[j]) << 4) + sub];
            ACC(r);
        }
        ++j;
    }
    ax += __shfl_xor_sync(0xffffffffu, ax, 16);
    ay += __shfl_xor_sync(0xffffffffu, ay, 16);
    az += __shfl_xor_sync(0xffffffffu, az, 16);
    aw += __shfl_xor_sync(0xffffffffu, aw, 16);
    return make_float4(ax, ay, az, aw);
}

// layers 0/1: s_out[v] = fp16( dinv[v]^2 * Σ s_in[src] )   [invariant: s = dinv ⊙ e]
__global__ void __launch_bounds__(256) k_prop(const __half2* __restrict__ in,
                                              __half2* __restrict__ out, int n) {
    int warp = (blockIdx.x * blockDim.x + threadIdx.x) >> 5;
    int lane = threadIdx.x & 31;
    if (warp >= n) return;
    int side = lane >> 4, sub = lane & 15;
    int lo = g_off[warp];
    float4 s = gather_sum2(reinterpret_cast<const uint2*>(in),
                           lo, lo + g_deg[warp], side, sub);
    if (side == 0) {
        float dv = g_dinv[warp];
        float d2 = dv * dv;
        __half2 oa = __float22half2_rn(make_float2(s.x * d2, s.y * d2));
        __half2 ob = __float22half2_rn(make_float2(s.z * d2, s.w * d2));
        uint2 o;
        o.x = *reinterpret_cast<unsigned*>(&oa);
        o.y = *reinterpret_cast<unsigned*>(&ob);
        reinterpret_cast<uint2*>(out)[(((size_t)warp) << 4) + sub] = o;
    }
}

// final: out = (emb0 + (s1+s2)*sqrt(deg) + dinv*Σ s2[src]) * 0.25; re-zero g_deg
__global__ void __launch_bounds__(256) k_final(const float* __restrict__ emb0,
                                               float* __restrict__ outp, int n) {
    int warp = (blockIdx.x * blockDim.x + threadIdx.x) >> 5;
    int lane = threadIdx.x & 31;
    if (warp >= n) return;
    int side = lane >> 4, sub = lane & 15;
    int lo = g_off[warp];
    int dg = g_deg[warp];
    float4 s = gather_sum2(reinterpret_cast<const uint2*>(g_s2),
                           lo, lo + dg, side, sub);

    if (side == 0) {
        float dv = g_dinv[warp];
        float sq = sqrtf((float)dg);               // e_k = s_k * sqrt(deg)
        size_t ro = (((size_t)warp) << 4) + sub;
        float4 e0 = reinterpret_cast<const float4*>(emb0)[ro];
        uint2 r1 = reinterpret_cast<const uint2*>(g_s1)[ro];
        uint2 r2 = reinterpret_cast<const uint2*>(g_s2)[ro];
        float2 a1a = __half22float2(*reinterpret_cast<__half2*>(&r1.x));
        float2 a1b = __half22float2(*reinterpret_cast<__half2*>(&r1.y));
        float2 a2a = __half22float2(*reinterpret_cast<__half2*>(&r2.x));
        float2 a2b = __half22float2(*reinterpret_cast<__half2*>(&r2.y));
        float4 r;
        r.x = (e0.x + (a1a.x + a2a.x) * sq + s.x * dv) * 0.25f;
        r.y = (e0.y + (a1a.y + a2a.y) * sq + s.y * dv) * 0.25f;
        r.z = (e0.z + (a1b.x + a2b.x) * sq + s.z * dv) * 0.25f;
        r.w = (e0.w + (a1b.y + a2b.y) * sq + s.w * dv) * 0.25f;
        reinterpret_cast<float4*>(outp)[ro] = r;
    }
    if (lane == 0) g_deg[warp] = 0;   // restore invariant for next graph replay
}

extern "C" void kernel_launch(void* const* d_in, const int* in_sizes, int n_in,
                              void* d_out, int out_size) {
    const int*   edges = (const int*)d_in[0];       // int32
    const float* emb   = (const float*)d_in[1];
    int E = in_sizes[0] / 2;
    int N = in_sizes[1] / D;

    const int* src = edges;
    const int* dst = edges + E;

    float* out0 = (float*)d_out;
    float* outp = out0 + (size_t)N * D;

    int tb = 256;
    int nbE4 = ((E + 3) / 4 + tb - 1) / tb;         // 4 edges per thread
    int NB   = (N + SCAN_T - 1) / SCAN_T;
    int n4   = (N * D) / 4;

    k_count<<<nbE4, tb>>>(dst, E, (const float4*)emb, (float4*)out0, n4); // 0 (+out0 copy)
    k_scanA<<<NB, SCAN_T>>>(N);                                           // 1
    k_scanBC<<<NB, SCAN_T>>>(N, NB);                                      // 2 (light)
    k_fill<<<nbE4, tb>>>(src, dst, E, (const float4*)emb, n4);            // 3 (+s0 build)

    __half2 *s0p, *s1p, *s2p;
    cudaGetSymbolAddress((void**)&s0p, g_s0);
    cudaGetSymbolAddress((void**)&s1p, g_s1);
    cudaGetSymbolAddress((void**)&s2p, g_s2);

    int pthreads = N * 32;                          // one warp per node
    int pblocks  = (pthreads + tb - 1) / tb;
    k_prop<<<pblocks, tb>>>(s0p, s1p, N);           // 4
    k_prop<<<pblocks, tb>>>(s1p, s2p, N);           // 5
    k_final<<<pblocks, tb>>>(emb, outp, N);         // 6
}

// round 15
// speedup vs baseline: 1.1171x; 1.0013x over previous
#include <cuda_runtime.h>
#include <cuda_fp16.h>
#include <cstdint>

#define D 64
#define N_MAX 200000
#define E_MAX 4000000
#define SCAN_T 1024

// ---- scratch (static device globals; zero-initialized at module load) ----
__device__ int     g_deg[N_MAX];       // zeroed at load; re-zeroed by k_final each call
__device__ int     g_off[N_MAX];
__device__ float   g_dinv[N_MAX];
__device__ __align__(16) int g_pr[E_MAX];       // packed (dst<<12)|rank
__device__ __align__(16) int g_src[E_MAX];      // CSR adjacency: src only
__device__ __half2 g_s0[(size_t)N_MAX * 32];    // s0 = dinv ⊙ emb0 (fp16)
__device__ __half2 g_s1[(size_t)N_MAX * 32];    // s1 = dinv ⊙ e1
__device__ __half2 g_s2[(size_t)N_MAX * 32];    // s2 = dinv ⊙ e2
__device__ int          g_bsum[256];
__device__ volatile int g_bflag[256];           // lookback flags; reset by k_final

// ------- degree count + packed rank record (4 edges/thread) + fused out0 copy -------
__global__ void k_count(const int* __restrict__ dst, int E,
                        const float4* __restrict__ emb, float4* __restrict__ o0,
                        int n4) {
    int tid = blockIdx.x * blockDim.x + threadIdx.x;
    int i = tid * 4;
    if (i + 3 < E) {
        int4 d = *reinterpret_cast<const int4*>(dst + i);
        int4 p;
        p.x = (d.x << 12) | atomicAdd(&g_deg[d.x], 1);
        p.y = (d.y << 12) | atomicAdd(&g_deg[d.y], 1);
        p.z = (d.z << 12) | atomicAdd(&g_deg[d.z], 1);
        p.w = (d.w << 12) | atomicAdd(&g_deg[d.w], 1);
        *reinterpret_cast<int4*>(g_pr + i) = p;
    } else {
        for (int k = i; k < E; ++k) {
            int d = dst[k];
            g_pr[k] = (d << 12) | atomicAdd(&g_deg[d], 1);
        }
    }
    // fused: out0 = emb0 (independent streaming work in the atomic shadow)
    int stride = gridDim.x * blockDim.x;
    for (int k = tid; k < n4; k += stride) o0[k] = emb[k];
}

// ------- single-pass exclusive scan (decoupled lookback) + dinv fused -------
__global__ void k_scan(int n, int nb) {
    __shared__ int s[SCAN_T];
    __shared__ int s_excl;
    int t = threadIdx.x;
    int b = blockIdx.x;
    int i = b * SCAN_T + t;
    int v = (i < n) ? g_deg[i] : 0;
    s[t] = v;
    __syncthreads();
    for (int d = 1; d < SCAN_T; d <<= 1) {
        int x = (t >= d) ? s[t - d] : 0;
        __syncthreads();
        s[t] += x;
        __syncthreads();
    }
    // publish this block's aggregate
    if (t == SCAN_T - 1) {
        g_bsum[b] = s[t];
        __threadfence();
        g_bflag[b] = 1;
    }
    // lookback: thread t < b spins on predecessor t's flag, then reduce
    int part = 0;
    if (t < b) {
        while (g_bflag[t] == 0) { }
        part = g_bsum[t];
    }
    // warp + smem reduction of partials over first nb threads
    for (int o = 16; o > 0; o >>= 1) part += __shfl_down_sync(0xffffffffu, part, o);
    __shared__ int wsum[32];
    if ((t & 31) == 0) wsum[t >> 5] = part;
    __syncthreads();
    if (t < 32) {
        int x = (t < (SCAN_T / 32)) ? wsum[t] : 0;
        for (int o = 16; o > 0; o >>= 1) x += __shfl_down_sync(0xffffffffu, x, o);
        if (t == 0) s_excl = x;
    }
    __syncthreads();
    if (i < n) {
        g_off[i]  = s[t] - v + s_excl;
        g_dinv[i] = (v > 0) ? rsqrtf((float)v) : 0.0f;
    }
}

// ------- CSR fill from packed rank (no dst read, no atomic) + fused s0 build -------
__global__ void k_fill(const int* __restrict__ src, int E,
                       const float4* __restrict__ emb, int n4) {
    int tid = blockIdx.x * blockDim.x + threadIdx.x;
    int i = tid * 4;
    if (i + 3 < E) {
        int4 s = *reinterpret_cast<const int4*>(src + i);
        int4 p = *reinterpret_cast<const int4*>(g_pr + i);
        g_src[g_off[p.x >> 12] + (p.x & 4095)] = s.x;
        g_src[g_off[p.y >> 12] + (p.y & 4095)] = s.y;
        g_src[g_off[p.z >> 12] + (p.z & 4095)] = s.z;
        g_src[g_off[p.w >> 12] + (p.w & 4095)] = s.w;
    } else {
        for (int k = i; k < E; ++k) {
            int p = g_pr[k];
            g_src[g_off[p >> 12] + (p & 4095)] = src[k];
        }
    }
    // fused: g_s0 = fp16(dinv ⊙ emb0)
    int stride = gridDim.x * blockDim.x;
    for (int k = tid; k < n4; k += stride) {
        float4 v = emb[k];
        float dv = g_dinv[k >> 4];                 // 16 float4 per node row
        g_s0[2 * k]     = __float22half2_rn(make_float2(v.x * dv, v.y * dv));
        g_s0[2 * k + 1] = __float22half2_rn(make_float2(v.z * dv, v.w * dv));
    }
}

// ---------------- gather-sum: warp per node, half-warp per edge (R11 optimum) ----------------
#define ACC(r) do { \
    float2 _fa = __half22float2(*reinterpret_cast<__half2*>(&(r).x)); \
    float2 _fb = __half22float2(*reinterpret_cast<__half2*>(&(r).y)); \
    ax += _fa.x; ay += _fa.y; az += _fb.x; aw += _fb.y; } while (0)

__device__ __forceinline__ float4 gather_sum2(const uint2* __restrict__ in2,
                                              int lo, int end, int side, int sub) {
    float ax = 0.f, ay = 0.f, az = 0.f, aw = 0.f;
    int j = lo;
    while (j < end && (j & 3)) {
        if ((j & 1) == side) {
            uint2 r = in2[(((size_t)g_src[j]) << 4) + sub];
            ACC(r);
        }
        ++j;
    }
    const int4* __restrict__ s4 = reinterpret_cast<const int4*>(g_src);
    for (; j + 16 <= end; j += 16) {
        int4 a = s4[(j >> 2) + 0];
        int4 b = s4[(j >> 2) + 1];
        int4 c = s4[(j >> 2) + 2];
        int4 d = s4[(j >> 2) + 3];
        int i0 = side ? a.y : a.x;
        int i1 = side ? a.w : a.z;
        int i2 = side ? b.y : b.x;
        int i3 = side ? b.w : b.z;
        int i4 = side ? c.y : c.x;
        int i5 = side ? c.w : c.z;
        int i6 = side ? d.y : d.x;
        int i7 = side ? d.w : d.z;
        uint2 r0 = in2[(((size_t)i0) << 4) + sub];
        uint2 r1 = in2[(((size_t)i1) << 4) + sub];
        uint2 r2 = in2[(((size_t)i2) << 4) + sub];
        uint2 r3 = in2[(((size_t)i3) << 4) + sub];
        uint2 r4 = in2[(((size_t)i4) << 4) + sub];
        uint2 r5 = in2[(((size_t)i5) << 4) + sub];
        uint2 r6 = in2[(((size_t)i6) << 4) + sub];
        uint2 r7 = in2[(((size_t)i7) << 4) + sub];
        ACC(r0); ACC(r1); ACC(r2); ACC(r3);
        ACC(r4); ACC(r5); ACC(r6); ACC(r7);
    }
    for (; j + 4 <= end; j += 4) {
        int4 a = s4[j >> 2];
        int i0 = side ? a.y : a.x;
        int i1 = side ? a.w : a.z;
        uint2 r0 = in2[(((size_t)i0) << 4) + sub];
        uint2 r1 = in2[(((size_t)i1) << 4) + sub];
        ACC(r0); ACC(r1);
    }
    while (j < end) {
        if ((j & 1) == side) {
            uint2 r = in2[(((size_t)g_src[j]) << 4) + sub];
            ACC(r);
        }
        ++j;
    }
    ax += __shfl_xor_sync(0xffffffffu, ax, 16);
    ay += __shfl_xor_sync(0xffffffffu, ay, 16);
    az += __shfl_xor_sync(0xffffffffu, az, 16);
    aw += __shfl_xor_sync(0xffffffffu, aw, 16);
    return make_float4(ax, ay, az, aw);
}

// layers 0/1: s_out[v] = fp16( dinv[v]^2 * Σ s_in[src] )   [invariant: s = dinv ⊙ e]
__global__ void __launch_bounds__(256) k_prop(const __half2* __restrict__ in,
                                              __half2* __restrict__ out, int n) {
    int warp = (blockIdx.x * blockDim.x + threadIdx.x) >> 5;
    int lane = threadIdx.x & 31;
    if (warp >= n) return;
    int side = lane >> 4, sub = lane & 15;
    int lo = g_off[warp];
    float4 s = gather_sum2(reinterpret_cast<const uint2*>(in),
                           lo, lo + g_deg[warp], side, sub);
    if (side == 0) {
        float dv = g_dinv[warp];
        float d2 = dv * dv;
        __half2 oa = __float22half2_rn(make_float2(s.x * d2, s.y * d2));
        __half2 ob = __float22half2_rn(make_float2(s.z * d2, s.w * d2));
        uint2 o;
        o.x = *reinterpret_cast<unsigned*>(&oa);
        o.y = *reinterpret_cast<unsigned*>(&ob);
        reinterpret_cast<uint2*>(out)[(((size_t)warp) << 4) + sub] = o;
    }
}

// final: out = (emb0 + (s1+s2)*sqrt(deg) + dinv*Σ s2[src]) * 0.25; reset g_deg/g_bflag
__global__ void __launch_bounds__(256) k_final(const float* __restrict__ emb0,
                                               float* __restrict__ outp, int n) {
    int warp = (blockIdx.x * blockDim.x + threadIdx.x) >> 5;
    int lane = threadIdx.x & 31;
    if (blockIdx.x == 0 && threadIdx.x < 256) g_bflag[threadIdx.x] = 0;  // reset lookback flags
    if (warp >= n) return;
    int side = lane >> 4, sub = lane & 15;
    int lo = g_off[warp];
    int dg = g_deg[warp];
    float4 s = gather_sum2(reinterpret_cast<const uint2*>(g_s2),
                           lo, lo + dg, side, sub);

    if (side == 0) {
        float dv = g_dinv[warp];
        float sq = sqrtf((float)dg);               // e_k = s_k * sqrt(deg)
        size_t ro = (((size_t)warp) << 4) + sub;
        float4 e0 = reinterpret_cast<const float4*>(emb0)[ro];
        uint2 r1 = reinterpret_cast<const uint2*>(g_s1)[ro];
        uint2 r2 = reinterpret_cast<const uint2*>(g_s2)[ro];
        float2 a1a = __half22float2(*reinterpret_cast<__half2*>(&r1.x));
        float2 a1b = __half22float2(*reinterpret_cast<__half2*>(&r1.y));
        float2 a2a = __half22float2(*reinterpret_cast<__half2*>(&r2.x));
        float2 a2b = __half22float2(*reinterpret_cast<__half2*>(&r2.y));
        float4 r;
        r.x = (e0.x + (a1a.x + a2a.x) * sq + s.x * dv) * 0.25f;
        r.y = (e0.y + (a1a.y + a2a.y) * sq + s.y * dv) * 0.25f;
        r.z = (e0.z + (a1b.x + a2b.x) * sq + s.z * dv) * 0.25f;
        r.w = (e0.w + (a1b.y + a2b.y) * sq + s.w * dv) * 0.25f;
        reinterpret_cast<float4*>(outp)[ro] = r;
    }
    if (lane == 0) g_deg[warp] = 0;   // restore invariant for next graph replay
}

extern "C" void kernel_launch(void* const* d_in, const int* in_sizes, int n_in,
                              void* d_out, int out_size) {
    const int*   edges = (const int*)d_in[0];       // int32
    const float* emb   = (const float*)d_in[1];
    int E = in_sizes[0] / 2;
    int N = in_sizes[1] / D;

    const int* src = edges;
    const int* dst = edges + E;

    float* out0 = (float*)d_out;
    float* outp = out0 + (size_t)N * D;

    int tb = 256;
    int nbE4 = ((E + 3) / 4 + tb - 1) / tb;         // 4 edges per thread
    int NB   = (N + SCAN_T - 1) / SCAN_T;           // 196
    int n4   = (N * D) / 4;

    k_count<<<nbE4, tb>>>(dst, E, (const float4*)emb, (float4*)out0, n4); // 0 (+out0)
    k_scan<<<NB, SCAN_T>>>(N, NB);                                        // 1 (scan+dinv)
    k_fill<<<nbE4, tb>>>(src, E, (const float4*)emb, n4);                 // 2 (+s0)

    __half2 *s0p, *s1p, *s2p;
    cudaGetSymbolAddress((void**)&s0p, g_s0);
    cudaGetSymbolAddress((void**)&s1p, g_s1);
    cudaGetSymbolAddress((void**)&s2p, g_s2);

    int pthreads = N * 32;                          // one warp per node
    int pblocks  = (pthreads + tb - 1) / tb;
    k_prop<<<pblocks, tb>>>(s0p, s1p, N);           // 3  <- profiled launch
    k_prop<<<pblocks, tb>>>(s1p, s2p, N);           // 4
    k_final<<<pblocks, tb>>>(emb, outp, N);         // 5
}